// round 1
// baseline (speedup 1.0000x reference)
#include <cuda_runtime.h>
#include <cstdint>
#include <math.h>

#define N_NODES 100000
#define N_EDGES 1600000
#define IN_DIM 256
#define HID 64
#define ALPHA 0.1f
#define EOSF 1e-10f
#define BIASF 1e-4f

// output layout: [w_lp_norm (E+N)] [w_hp_norm (E+N)] [weights_lp (E)] [weights_hp (E)]
#define OFF_LPN 0
#define OFF_HPN (N_EDGES + N_NODES)
#define OFF_WLP (2 * (N_EDGES + N_NODES))
#define OFF_WHP (2 * (N_EDGES + N_NODES) + N_EDGES)

// scratch (no allocations allowed)
__device__ float g_q[N_NODES];
__device__ float g_deg_lo[N_NODES];
__device__ float g_deg_li[N_NODES];
__device__ float g_deg_ho[N_NODES];
__device__ float g_deg_hi[N_NODES];
__device__ int   g_is64;

// ---------------------------------------------------------------------------
// packed f32x2 helpers (B300: fma.rn.f32x2 doubles FFMA throughput vs 3-reg FFMA)
// ---------------------------------------------------------------------------
__device__ __forceinline__ unsigned long long pack2(float lo, float hi) {
    unsigned long long r;
    asm("mov.b64 %0, {%1, %2};" : "=l"(r) : "f"(lo), "f"(hi));
    return r;
}
__device__ __forceinline__ void fma2(unsigned long long& d, unsigned long long a,
                                     unsigned long long b) {
    asm("fma.rn.f32x2 %0, %1, %2, %0;" : "+l"(d) : "l"(a), "l"(b));
}
__device__ __forceinline__ void unpack2(unsigned long long v, float& lo, float& hi) {
    asm("mov.b64 {%0, %1}, %2;" : "=f"(lo), "=f"(hi) : "l"(v));
}

// ---------------------------------------------------------------------------
// Detect whether edges are int64 (odd 32-bit words all zero) or int32.
// ---------------------------------------------------------------------------
__global__ void detect_kernel(const unsigned int* __restrict__ w) {
    if (threadIdx.x == 0) {
        bool z = true;
#pragma unroll
        for (int i = 1; i < 16; i += 2) z = z && (w[i] == 0u);
        g_is64 = z ? 1 : 0;
    }
}

__device__ __forceinline__ int edge_at(const void* p, long long i, int is64) {
    if (is64) return (int)(((const long long*)p)[i]);
    return ((const int*)p)[i];
}

// ---------------------------------------------------------------------------
// Init degree arrays: every node has a self loop with weight 1 (+EOS)
// ---------------------------------------------------------------------------
__global__ void init_deg_kernel() {
    int i = blockIdx.x * blockDim.x + threadIdx.x;
    if (i < N_NODES) {
        float v = 1.0f + EOSF;
        g_deg_lo[i] = v;
        g_deg_li[i] = v;
        g_deg_ho[i] = v;
        g_deg_hi[i] = v;
    }
}

// ---------------------------------------------------------------------------
// Fused node embedding:  q[n] = sum_j relu(feat[n,:] @ Wemb[:,j] + bemb[j]) * wc[j]
// with wc[j] = Wedge[j] + Wedge[64+j].
// 128x64 block tile, K-tile 32, 8(M)x4(N) register tile per thread,
// A transposed in smem so M-pairs feed fma.rn.f32x2.
// ---------------------------------------------------------------------------
__global__ __launch_bounds__(256) void embed_kernel(
    const float* __restrict__ feat, const float* __restrict__ Wemb,
    const float* __restrict__ bemb, const float* __restrict__ Wedge) {
    constexpr int BM = 128, BK = 32, LDA = BM + 2;  // LDA even -> 8B-aligned rows
    __shared__ __align__(16) float As[BK][LDA];     // transposed: As[k][m]
    __shared__ __align__(16) float Bs[BK][HID];

    const int tid = threadIdx.x;
    const int tx = tid & 15;   // hidden group: 4 cols each
    const int ty = tid >> 4;   // node group: 8 rows each
    const int row0 = blockIdx.x * BM;

    unsigned long long acc2[4][4];  // [m-pair][n] packed (m=2p, m=2p+1)
#pragma unroll
    for (int p = 0; p < 4; p++)
#pragma unroll
        for (int j = 0; j < 4; j++) acc2[p][j] = 0ull;

    for (int k0 = 0; k0 < IN_DIM; k0 += BK) {
        // load A tile (128 nodes x 32 k), transposed into smem
#pragma unroll
        for (int l = 0; l < 4; l++) {
            int idx = tid + l * 256;     // float4 index 0..1023
            int m = idx >> 3;            // 8 float4 per node-row
            int k4 = idx & 7;
            int node = row0 + m;
            float4 v = make_float4(0.f, 0.f, 0.f, 0.f);
            if (node < N_NODES)
                v = *(const float4*)&feat[(size_t)node * IN_DIM + k0 + k4 * 4];
            As[k4 * 4 + 0][m] = v.x;
            As[k4 * 4 + 1][m] = v.y;
            As[k4 * 4 + 2][m] = v.z;
            As[k4 * 4 + 3][m] = v.w;
        }
        // load B tile (32 k x 64 hid)
#pragma unroll
        for (int l = 0; l < 2; l++) {
            int idx = tid + l * 256;     // float4 index, 16 per row
            int r = idx >> 4;
            int c4 = idx & 15;
            *(float4*)&Bs[r][c4 * 4] =
                *(const float4*)&Wemb[(size_t)(k0 + r) * HID + c4 * 4];
        }
        __syncthreads();

#pragma unroll
        for (int kk = 0; kk < BK; kk++) {
            unsigned long long a2[4];
#pragma unroll
            for (int p = 0; p < 4; p++)
                a2[p] = *(const unsigned long long*)&As[kk][ty * 8 + p * 2];
            float4 bv = *(const float4*)&Bs[kk][tx * 4];
            unsigned long long b2[4];
            b2[0] = pack2(bv.x, bv.x);
            b2[1] = pack2(bv.y, bv.y);
            b2[2] = pack2(bv.z, bv.z);
            b2[3] = pack2(bv.w, bv.w);
#pragma unroll
            for (int p = 0; p < 4; p++)
#pragma unroll
                for (int j = 0; j < 4; j++) fma2(acc2[p][j], a2[p], b2[j]);
        }
        __syncthreads();
    }

    // epilogue: bias + relu + dot with wc, reduce across the 16 tx lanes
    float bb[4], wc[4];
#pragma unroll
    for (int j = 0; j < 4; j++) {
        int n = tx * 4 + j;
        bb[j] = bemb[n];
        wc[j] = Wedge[n] + Wedge[HID + n];
    }
#pragma unroll
    for (int p = 0; p < 4; p++) {
        float alo[4], ahi[4];
#pragma unroll
        for (int j = 0; j < 4; j++) unpack2(acc2[p][j], alo[j], ahi[j]);
#pragma unroll
        for (int half = 0; half < 2; half++) {
            float s = 0.f;
#pragma unroll
            for (int j = 0; j < 4; j++) {
                float h = (half ? ahi[j] : alo[j]) + bb[j];
                h = fmaxf(h, 0.f);
                s = fmaf(h, wc[j], s);
            }
#pragma unroll
            for (int off = 1; off < 16; off <<= 1)
                s += __shfl_xor_sync(0xffffffffu, s, off, 16);
            if (tx == 0) {
                int node = row0 + ty * 8 + p * 2 + half;
                if (node < N_NODES) g_q[node] = s;
            }
        }
    }
}

// ---------------------------------------------------------------------------
// Edge pass 1: gumbel-sigmoid weights + degree scatter-adds
// ---------------------------------------------------------------------------
__global__ __launch_bounds__(256) void edge_weights_kernel(
    const void* __restrict__ edges, const float* __restrict__ noise,
    const float* __restrict__ b_edge_p, float* __restrict__ out) {
    int e = blockIdx.x * blockDim.x + threadIdx.x;
    if (e >= N_EDGES) return;
    const int is64 = g_is64;
    int src = edge_at(edges, e, is64);
    int dst = edge_at(edges, (long long)N_EDGES + e, is64);
    float b_edge = *b_edge_p;
    float raw = 0.5f * (g_q[src] + g_q[dst]) + b_edge;
    float u = noise[e];
    float eps = fmaf(2.0f * BIASF - 1.0f, u, 1.0f - BIASF);
    float gate = logf(eps) - log1pf(-eps);
    float x = gate + raw;                      // TEMP = 1
    float wlp = 1.0f / (1.0f + expf(-x));
    float whp = 1.0f - wlp;                    // matches reference cancellation
    out[OFF_WLP + e] = wlp;
    out[OFF_WHP + e] = whp;
    float wl = wlp + EOSF, wh = whp + EOSF;
    atomicAdd(&g_deg_lo[src], wl);
    atomicAdd(&g_deg_li[dst], wl);
    atomicAdd(&g_deg_ho[src], wh);
    atomicAdd(&g_deg_hi[dst], wh);
}

// ---------------------------------------------------------------------------
// Edge pass 2: normalize by sqrt(deg_out[src]*deg_in[dst]); self loops at tail
// ---------------------------------------------------------------------------
__global__ __launch_bounds__(256) void edge_norm_kernel(
    const void* __restrict__ edges, float* __restrict__ out) {
    int e = blockIdx.x * blockDim.x + threadIdx.x;
    if (e < N_EDGES) {
        const int is64 = g_is64;
        int src = edge_at(edges, e, is64);
        int dst = edge_at(edges, (long long)N_EDGES + e, is64);
        float wl = out[OFF_WLP + e] + EOSF;
        float wh = out[OFF_WHP + e] + EOSF;
        float dl = g_deg_lo[src] * g_deg_li[dst];
        float dh = g_deg_ho[src] * g_deg_hi[dst];
        out[OFF_LPN + e] = wl / sqrtf(dl);
        out[OFF_HPN + e] = (wh / sqrtf(dh)) * (-ALPHA);
    } else if (e < N_EDGES + N_NODES) {
        int i = e - N_EDGES;
        float wl = 1.0f + EOSF;
        float dl = g_deg_lo[i] * g_deg_li[i];
        out[OFF_LPN + e] = wl / sqrtf(dl);
        out[OFF_HPN + e] = 1.0f;  // hp self-loop weights forced to 1
    }
}

// ---------------------------------------------------------------------------
extern "C" void kernel_launch(void* const* d_in, const int* in_sizes, int n_in,
                              void* d_out, int out_size) {
    const float* features = (const float*)d_in[0];
    const void*  edges    = d_in[1];
    const float* noise    = (const float*)d_in[2];
    const float* Wemb     = (const float*)d_in[3];
    const float* bemb     = (const float*)d_in[4];
    const float* Wedge    = (const float*)d_in[5];
    const float* bedge    = (const float*)d_in[6];
    float* out = (float*)d_out;

    detect_kernel<<<1, 32>>>((const unsigned int*)edges);
    init_deg_kernel<<<(N_NODES + 255) / 256, 256>>>();
    embed_kernel<<<(N_NODES + 127) / 128, 256>>>(features, Wemb, bemb, Wedge);
    edge_weights_kernel<<<(N_EDGES + 255) / 256, 256>>>(edges, noise, bedge, out);
    edge_norm_kernel<<<(N_EDGES + N_NODES + 255) / 256, 256>>>(edges, out);
}

// round 2
// speedup vs baseline: 1.1770x; 1.1770x over previous
#include <cuda_runtime.h>
#include <cstdint>
#include <math.h>

#define N_NODES 100000
#define N_EDGES 1600000
#define IN_DIM 256
#define HID 64
#define ALPHA 0.1f
#define EOSF 1e-10f
#define BIASF 1e-4f

// output layout: [w_lp_norm (E+N)] [w_hp_norm (E+N)] [weights_lp (E)] [weights_hp (E)]
#define OFF_LPN 0
#define OFF_HPN (N_EDGES + N_NODES)
#define OFF_WLP (2 * (N_EDGES + N_NODES))
#define OFF_WHP (2 * (N_EDGES + N_NODES) + N_EDGES)

// fixed-point packed degree accumulator: count at bit 44, sum(wlp)*2^32 in low 44 bits
#define CNT_SHIFT 44
#define SUM_MASK ((1ULL << CNT_SHIFT) - 1ULL)
#define SUM_SCALE 4294967296.0f           // 2^32
#define SUM_INV (1.0f / 4294967296.0f)

// scratch (no allocations allowed)
__device__ float g_q[N_NODES];
__device__ unsigned long long g_acc_out[N_NODES];
__device__ unsigned long long g_acc_in[N_NODES];
__device__ __align__(16) float2 g_ro[N_NODES];   // {rsqrt(deg_lo_out), rsqrt(deg_ho_out)}
__device__ __align__(16) float2 g_ri[N_NODES];   // {rsqrt(deg_lo_in),  rsqrt(deg_ho_in)}
__device__ __align__(16) int g_src[N_EDGES];
__device__ __align__(16) int g_dst[N_EDGES];
__device__ int g_is64;

// ---------------------------------------------------------------------------
// packed f32x2 helpers (B300: fma.rn.f32x2 doubles FFMA throughput)
// ---------------------------------------------------------------------------
__device__ __forceinline__ unsigned long long pack2(float lo, float hi) {
    unsigned long long r;
    asm("mov.b64 %0, {%1, %2};" : "=l"(r) : "f"(lo), "f"(hi));
    return r;
}
__device__ __forceinline__ void fma2(unsigned long long& d, unsigned long long a,
                                     unsigned long long b) {
    asm("fma.rn.f32x2 %0, %1, %2, %0;" : "+l"(d) : "l"(a), "l"(b));
}
__device__ __forceinline__ void unpack2(unsigned long long v, float& lo, float& hi) {
    asm("mov.b64 {%0, %1}, %2;" : "=f"(lo), "=f"(hi) : "l"(v));
}

// ---------------------------------------------------------------------------
// Detect whether edges are int64 (odd 32-bit words all zero) or int32.
// ---------------------------------------------------------------------------
__global__ void detect_kernel(const unsigned int* __restrict__ w) {
    if (threadIdx.x == 0) {
        bool z = true;
#pragma unroll
        for (int i = 1; i < 16; i += 2) z = z && (w[i] == 0u);
        g_is64 = z ? 1 : 0;
    }
}

// ---------------------------------------------------------------------------
// Fused node embedding:  q[n] = sum_j relu(feat[n,:] @ Wemb[:,j] + bemb[j]) * wc[j]
// 128x64 tile, BK=32, 8(M)x4(N) per thread via fma.rn.f32x2, register
// double-buffered global loads. Also zeroes the degree accumulators.
// ---------------------------------------------------------------------------
__global__ __launch_bounds__(256, 2) void embed_kernel(
    const float* __restrict__ feat, const float* __restrict__ Wemb,
    const float* __restrict__ bemb, const float* __restrict__ Wedge) {
    constexpr int BM = 128, BK = 32, LDA = BM + 2;
    __shared__ __align__(16) float As[BK][LDA];   // transposed: As[k][m]
    __shared__ __align__(16) float Bs[BK][HID];

    const int tid = threadIdx.x;
    const int tx = tid & 15;   // hidden group: 4 cols each
    const int ty = tid >> 4;   // node group: 8 rows each
    const int row0 = blockIdx.x * BM;

    // zero packed degree accumulators for this block's nodes
    if (tid < BM) {
        int n = row0 + tid;
        if (n < N_NODES) { g_acc_out[n] = 0ull; g_acc_in[n] = 0ull; }
    }

    // per-thread load coordinates
    int am[4], ak4[4];
    const float* aptr[4];
    bool aval[4];
#pragma unroll
    for (int l = 0; l < 4; l++) {
        int idx = tid + l * 256;
        am[l] = idx >> 3;          // node within tile
        ak4[l] = idx & 7;          // float4 within k-tile
        int node = row0 + am[l];
        aval[l] = node < N_NODES;
        aptr[l] = feat + (size_t)(aval[l] ? node : 0) * IN_DIM + ak4[l] * 4;
    }
    int br[2], bc[2];
#pragma unroll
    for (int l = 0; l < 2; l++) {
        int idx = tid + l * 256;
        br[l] = idx >> 4;
        bc[l] = idx & 15;
    }

    unsigned long long acc2[4][4];
#pragma unroll
    for (int p = 0; p < 4; p++)
#pragma unroll
        for (int j = 0; j < 4; j++) acc2[p][j] = 0ull;

    float4 ra[4], rb[2];
    // prologue loads (k0 = 0)
#pragma unroll
    for (int l = 0; l < 4; l++)
        ra[l] = aval[l] ? *(const float4*)(aptr[l]) : make_float4(0.f, 0.f, 0.f, 0.f);
#pragma unroll
    for (int l = 0; l < 2; l++)
        rb[l] = *(const float4*)&Wemb[(size_t)br[l] * HID + bc[l] * 4];

    constexpr int NT = IN_DIM / BK;  // 8
#pragma unroll 1
    for (int t = 0; t < NT; t++) {
        // stage registers -> smem
#pragma unroll
        for (int l = 0; l < 4; l++) {
            As[ak4[l] * 4 + 0][am[l]] = ra[l].x;
            As[ak4[l] * 4 + 1][am[l]] = ra[l].y;
            As[ak4[l] * 4 + 2][am[l]] = ra[l].z;
            As[ak4[l] * 4 + 3][am[l]] = ra[l].w;
        }
#pragma unroll
        for (int l = 0; l < 2; l++) *(float4*)&Bs[br[l]][bc[l] * 4] = rb[l];
        __syncthreads();

        // issue next tile's loads (overlap with compute below)
        if (t + 1 < NT) {
            int k0 = (t + 1) * BK;
#pragma unroll
            for (int l = 0; l < 4; l++)
                ra[l] = aval[l] ? *(const float4*)(aptr[l] + k0)
                                : make_float4(0.f, 0.f, 0.f, 0.f);
#pragma unroll
            for (int l = 0; l < 2; l++)
                rb[l] = *(const float4*)&Wemb[(size_t)(k0 + br[l]) * HID + bc[l] * 4];
        }

#pragma unroll
        for (int kk = 0; kk < BK; kk++) {
            unsigned long long a2[4];
#pragma unroll
            for (int p = 0; p < 4; p++)
                a2[p] = *(const unsigned long long*)&As[kk][ty * 8 + p * 2];
            float4 bv = *(const float4*)&Bs[kk][tx * 4];
            unsigned long long b2[4];
            b2[0] = pack2(bv.x, bv.x);
            b2[1] = pack2(bv.y, bv.y);
            b2[2] = pack2(bv.z, bv.z);
            b2[3] = pack2(bv.w, bv.w);
#pragma unroll
            for (int p = 0; p < 4; p++)
#pragma unroll
                for (int j = 0; j < 4; j++) fma2(acc2[p][j], a2[p], b2[j]);
        }
        __syncthreads();
    }

    // epilogue: bias + relu + dot with wc, reduce across 16 tx lanes
    float bb[4], wc[4];
#pragma unroll
    for (int j = 0; j < 4; j++) {
        int n = tx * 4 + j;
        bb[j] = bemb[n];
        wc[j] = Wedge[n] + Wedge[HID + n];
    }
#pragma unroll
    for (int p = 0; p < 4; p++) {
        float alo[4], ahi[4];
#pragma unroll
        for (int j = 0; j < 4; j++) unpack2(acc2[p][j], alo[j], ahi[j]);
#pragma unroll
        for (int half = 0; half < 2; half++) {
            float s = 0.f;
#pragma unroll
            for (int j = 0; j < 4; j++) {
                float h = (half ? ahi[j] : alo[j]) + bb[j];
                h = fmaxf(h, 0.f);
                s = fmaf(h, wc[j], s);
            }
#pragma unroll
            for (int off = 1; off < 16; off <<= 1)
                s += __shfl_xor_sync(0xffffffffu, s, off, 16);
            if (tx == 0) {
                int node = row0 + ty * 8 + p * 2 + half;
                if (node < N_NODES) g_q[node] = s;
            }
        }
    }
}

// ---------------------------------------------------------------------------
// Edge pass 1 (2 edges/thread): gumbel-sigmoid weights, int32 edge scratch,
// ONE packed 64-bit atomic per endpoint (count + fixed-point sum of wlp).
// ---------------------------------------------------------------------------
__device__ __forceinline__ float edge_w(float q_s, float q_d, float u, float be) {
    float raw = 0.5f * (q_s + q_d) + be;
    float eps = fmaf(2.0f * BIASF - 1.0f, u, 1.0f - BIASF);
    float gate = logf(eps) - log1pf(-eps);
    float x = gate + raw;  // TEMP = 1
    return 1.0f / (1.0f + expf(-x));
}

__global__ __launch_bounds__(256) void edge_weights_kernel(
    const void* __restrict__ edges, const float* __restrict__ noise,
    const float* __restrict__ b_edge_p, float* __restrict__ out) {
    int t = blockIdx.x * blockDim.x + threadIdx.x;
    if (t * 2 >= N_EDGES) return;

    int s0, s1, d0, d1;
    if (g_is64) {
        longlong2 sv = ((const longlong2*)edges)[t];
        longlong2 dv = ((const longlong2*)((const long long*)edges + N_EDGES))[t];
        s0 = (int)sv.x; s1 = (int)sv.y; d0 = (int)dv.x; d1 = (int)dv.y;
    } else {
        int2 sv = ((const int2*)edges)[t];
        int2 dv = ((const int2*)((const int*)edges + N_EDGES))[t];
        s0 = sv.x; s1 = sv.y; d0 = dv.x; d1 = dv.y;
    }
    ((int2*)g_src)[t] = make_int2(s0, s1);
    ((int2*)g_dst)[t] = make_int2(d0, d1);

    float2 u = ((const float2*)noise)[t];
    float be = *b_edge_p;
    float w0 = edge_w(g_q[s0], g_q[d0], u.x, be);
    float w1 = edge_w(g_q[s1], g_q[d1], u.y, be);

    ((float2*)(out + OFF_WLP))[t] = make_float2(w0, w1);
    ((float2*)(out + OFF_WHP))[t] = make_float2(1.0f - w0, 1.0f - w1);

    unsigned long long e0 = (1ULL << CNT_SHIFT) | (unsigned long long)(w0 * SUM_SCALE);
    unsigned long long e1 = (1ULL << CNT_SHIFT) | (unsigned long long)(w1 * SUM_SCALE);
    atomicAdd(&g_acc_out[s0], e0);
    atomicAdd(&g_acc_in[d0], e0);
    atomicAdd(&g_acc_out[s1], e1);
    atomicAdd(&g_acc_in[d1], e1);
}

// ---------------------------------------------------------------------------
// Node pass: decode packed degrees, precompute rsqrt factors, self-loop outputs
// ---------------------------------------------------------------------------
__global__ __launch_bounds__(256) void node_kernel(float* __restrict__ out) {
    int n = blockIdx.x * blockDim.x + threadIdx.x;
    if (n >= N_NODES) return;
    unsigned long long vo = g_acc_out[n], vi = g_acc_in[n];
    float co = (float)(vo >> CNT_SHIFT);
    float So = (float)(vo & SUM_MASK) * SUM_INV;
    float ci = (float)(vi >> CNT_SHIFT);
    float Si = (float)(vi & SUM_MASK) * SUM_INV;
    // deg = 1 (self loop) + sum over incident edges (EOS terms vanish in fp32)
    float2 ro = make_float2(rsqrtf(1.0f + So), rsqrtf(1.0f + co - So));
    float2 ri = make_float2(rsqrtf(1.0f + Si), rsqrtf(1.0f + ci - Si));
    g_ro[n] = ro;
    g_ri[n] = ri;
    out[OFF_LPN + N_EDGES + n] = (1.0f + EOSF) * ro.x * ri.x;
    out[OFF_HPN + N_EDGES + n] = 1.0f;  // hp self-loop forced to 1
}

// ---------------------------------------------------------------------------
// Edge pass 2 (2 edges/thread): normalize with precomputed float2 factors
// ---------------------------------------------------------------------------
__global__ __launch_bounds__(256) void edge_norm_kernel(float* __restrict__ out) {
    int t = blockIdx.x * blockDim.x + threadIdx.x;
    if (t * 2 >= N_EDGES) return;
    int2 s = ((const int2*)g_src)[t];
    int2 d = ((const int2*)g_dst)[t];
    float2 wl = ((const float2*)(out + OFF_WLP))[t];
    float2 wh = ((const float2*)(out + OFF_WHP))[t];
    float2 ro0 = g_ro[s.x], ro1 = g_ro[s.y];
    float2 ri0 = g_ri[d.x], ri1 = g_ri[d.y];
    ((float2*)(out + OFF_LPN))[t] =
        make_float2((wl.x + EOSF) * ro0.x * ri0.x, (wl.y + EOSF) * ro1.x * ri1.x);
    ((float2*)(out + OFF_HPN))[t] =
        make_float2(-ALPHA * (wh.x + EOSF) * ro0.y * ri0.y,
                    -ALPHA * (wh.y + EOSF) * ro1.y * ri1.y);
}

// ---------------------------------------------------------------------------
extern "C" void kernel_launch(void* const* d_in, const int* in_sizes, int n_in,
                              void* d_out, int out_size) {
    const float* features = (const float*)d_in[0];
    const void*  edges    = d_in[1];
    const float* noise    = (const float*)d_in[2];
    const float* Wemb     = (const float*)d_in[3];
    const float* bemb     = (const float*)d_in[4];
    const float* Wedge    = (const float*)d_in[5];
    const float* bedge    = (const float*)d_in[6];
    float* out = (float*)d_out;

    const int ET = N_EDGES / 2;  // 2 edges per thread
    detect_kernel<<<1, 32>>>((const unsigned int*)edges);
    embed_kernel<<<(N_NODES + 127) / 128, 256>>>(features, Wemb, bemb, Wedge);
    edge_weights_kernel<<<(ET + 255) / 256, 256>>>(edges, noise, bedge, out);
    node_kernel<<<(N_NODES + 255) / 256, 256>>>(out);
    edge_norm_kernel<<<(ET + 255) / 256, 256>>>(out);
}